// round 2
// baseline (speedup 1.0000x reference)
#include <cuda_runtime.h>

// PointNetSaModule: gather(K=16 neighbors) -> mask -> concat(xyz_diff, feats)
// -> [67->64->64->128] 1x1-conv MLP with folded BN + ReLU -> max over K.
// One thread = one (b,n,k) row. fp32 math via packed fma.rn.f32x2 (sm_103a).

typedef unsigned long long ULL;

#define B_SZ   4
#define HW_SZ  65536      // H*W
#define NS_SZ  16384      // h*w
#define K_SZ   16
#define OUTC   128
#define OUT_ONE (B_SZ * NS_SZ * OUTC)   // 8388608

#define THREADS 256
#define ROWSTRIDE 69      // 67 padded to odd stride -> conflict-free per-lane rows

// smem float offsets
#define OFF_W0   0                 // 67*64 = 4288
#define OFF_W1   (OFF_W0 + 4288)   // 64*64 = 4096
#define OFF_W2   (OFF_W1 + 4096)   // 64*128 = 8192
#define OFF_T0   (OFF_W2 + 8192)   // 64
#define OFF_T1   (OFF_T0 + 64)     // 64
#define OFF_T2   (OFF_T1 + 64)     // 128
#define OFF_S0   (OFF_T2 + 128)    // 64
#define OFF_S1   (OFF_S0 + 64)     // 64
#define OFF_S2   (OFF_S1 + 64)     // 128
#define OFF_ACT  (OFF_S2 + 128)    // 256*69 = 17664
#define SMEM_FLOATS (OFF_ACT + THREADS * ROWSTRIDE)
#define SMEM_BYTES  (SMEM_FLOATS * 4)

__device__ __forceinline__ ULL pack2_dup(float v) {
    ULL r; asm("mov.b64 %0, {%1, %1};" : "=l"(r) : "f"(v)); return r;
}
__device__ __forceinline__ ULL pack2(float a, float b) {
    ULL r; asm("mov.b64 %0, {%1, %2};" : "=l"(r) : "f"(a), "f"(b)); return r;
}
__device__ __forceinline__ float2 unpack2(ULL v) {
    float2 f; asm("mov.b64 {%0, %1}, %2;" : "=f"(f.x), "=f"(f.y) : "l"(v)); return f;
}
__device__ __forceinline__ void ffma2(ULL& acc, ULL x, ULL w) {
    asm("fma.rn.f32x2 %0, %1, %2, %0;" : "+l"(acc) : "l"(x), "l"(w));
}

__global__ void __launch_bounds__(THREADS, 1)
pointnet_sa_kernel(
    const float* __restrict__ xyz,     // (B, H*W, 3)
    const float* __restrict__ pts,     // (B, H*W, 64)
    const float* __restrict__ xyzs,    // (B, n, 3)
    const int*   __restrict__ nbr,     // (B, n*K)
    const float* __restrict__ vmask,   // (B, n, K, 1)
    const float* __restrict__ w0, const float* __restrict__ b0,
    const float* __restrict__ g0, const float* __restrict__ be0,
    const float* __restrict__ m0, const float* __restrict__ v0,
    const float* __restrict__ w1, const float* __restrict__ b1,
    const float* __restrict__ g1, const float* __restrict__ be1,
    const float* __restrict__ m1, const float* __restrict__ v1,
    const float* __restrict__ w2, const float* __restrict__ b2,
    const float* __restrict__ g2, const float* __restrict__ be2,
    const float* __restrict__ m2, const float* __restrict__ v2,
    float* __restrict__ out, int copies)
{
    extern __shared__ float sm[];
    const int tid = threadIdx.x;

    // ---- fold BN into scale s (pre-applied to weights) and shift t ----
    if (tid < 64) {
        float s = g0[tid] * rsqrtf(v0[tid] + 1e-5f);
        sm[OFF_S0 + tid] = s;
        sm[OFF_T0 + tid] = (b0[tid] - m0[tid]) * s + be0[tid];
        float s1 = g1[tid] * rsqrtf(v1[tid] + 1e-5f);
        sm[OFF_S1 + tid] = s1;
        sm[OFF_T1 + tid] = (b1[tid] - m1[tid]) * s1 + be1[tid];
    }
    if (tid < 128) {
        float s = g2[tid] * rsqrtf(v2[tid] + 1e-5f);
        sm[OFF_S2 + tid] = s;
        sm[OFF_T2 + tid] = (b2[tid] - m2[tid]) * s + be2[tid];
    }
    __syncthreads();
    for (int i = tid; i < 4288; i += THREADS) sm[OFF_W0 + i] = w0[i] * sm[OFF_S0 + (i & 63)];
    for (int i = tid; i < 4096; i += THREADS) sm[OFF_W1 + i] = w1[i] * sm[OFF_S1 + (i & 63)];
    for (int i = tid; i < 8192; i += THREADS) sm[OFF_W2 + i] = w2[i] * sm[OFF_S2 + (i & 127)];
    __syncthreads();

    // ---- identify row ----
    const int g  = blockIdx.x * (THREADS / K_SZ) + (tid >> 4);
    const int b  = g >> 14;
    const int n  = g & (NS_SZ - 1);
    const int k  = tid & (K_SZ - 1);
    const int e  = b * (NS_SZ * K_SZ) + n * K_SZ + k;
    const int idx = nbr[e];
    const float mk = vmask[e];

    float* xr = sm + OFF_ACT + tid * ROWSTRIDE;

    // ---- gather + mask + xyz diff into smem row ----
    {
        const float* cp = xyzs + (b * NS_SZ + n) * 3;
        const float* gx = xyz + (b * HW_SZ + idx) * 3;
        xr[0] = gx[0] * mk - cp[0];
        xr[1] = gx[1] * mk - cp[1];
        xr[2] = gx[2] * mk - cp[2];
        const float4* pp = (const float4*)(pts + (b * HW_SZ + idx) * 64);
        #pragma unroll
        for (int i = 0; i < 16; i++) {
            float4 p = pp[i];
            xr[3 + 4*i] = p.x * mk; xr[4 + 4*i] = p.y * mk;
            xr[5 + 4*i] = p.z * mk; xr[6 + 4*i] = p.w * mk;
        }
    }

    // ---- layer 0: 67 -> 64 (in-place: reads [0,67) complete before writes) ----
    {
        ULL acc[32];
        #pragma unroll
        for (int j = 0; j < 32; j++) acc[j] = 0ull;
        #pragma unroll 2
        for (int cin = 0; cin < 67; cin++) {
            ULL xx = pack2_dup(xr[cin]);
            const ulonglong2* wr = (const ulonglong2*)(sm + OFF_W0 + cin * 64);
            #pragma unroll
            for (int j = 0; j < 16; j++) {
                ulonglong2 w = wr[j];
                ffma2(acc[2*j],   xx, w.x);
                ffma2(acc[2*j+1], xx, w.y);
            }
        }
        #pragma unroll
        for (int j = 0; j < 32; j++) {
            float2 a = unpack2(acc[j]);
            xr[2*j]   = fmaxf(a.x + sm[OFF_T0 + 2*j],   0.f);
            xr[2*j+1] = fmaxf(a.y + sm[OFF_T0 + 2*j+1], 0.f);
        }
    }

    // ---- layer 1: 64 -> 64 ----
    {
        ULL acc[32];
        #pragma unroll
        for (int j = 0; j < 32; j++) acc[j] = 0ull;
        #pragma unroll 2
        for (int cin = 0; cin < 64; cin++) {
            ULL xx = pack2_dup(xr[cin]);
            const ulonglong2* wr = (const ulonglong2*)(sm + OFF_W1 + cin * 64);
            #pragma unroll
            for (int j = 0; j < 16; j++) {
                ulonglong2 w = wr[j];
                ffma2(acc[2*j],   xx, w.x);
                ffma2(acc[2*j+1], xx, w.y);
            }
        }
        #pragma unroll
        for (int j = 0; j < 32; j++) {
            float2 a = unpack2(acc[j]);
            xr[2*j]   = fmaxf(a.x + sm[OFF_T1 + 2*j],   0.f);
            xr[2*j+1] = fmaxf(a.y + sm[OFF_T1 + 2*j+1], 0.f);
        }
    }

    // ---- layer 2: 64 -> 128, fused bias+ReLU, max over K via shfl butterfly ----
    ULL acc[64];
    #pragma unroll
    for (int j = 0; j < 64; j++) acc[j] = 0ull;
    #pragma unroll 2
    for (int cin = 0; cin < 64; cin++) {
        ULL xx = pack2_dup(xr[cin]);
        const ulonglong2* wr = (const ulonglong2*)(sm + OFF_W2 + cin * 128);
        #pragma unroll
        for (int j = 0; j < 32; j++) {
            ulonglong2 w = wr[j];
            ffma2(acc[2*j],   xx, w.x);
            ffma2(acc[2*j+1], xx, w.y);
        }
    }
    #pragma unroll
    for (int j = 0; j < 64; j++) {
        float2 a = unpack2(acc[j]);
        a.x = fmaxf(a.x + sm[OFF_T2 + 2*j],   0.f);
        a.y = fmaxf(a.y + sm[OFF_T2 + 2*j+1], 0.f);
        acc[j] = pack2(a.x, a.y);
    }
    // butterfly max within each 16-lane group (offsets stay inside the half-warp)
    #pragma unroll
    for (int off = 8; off >= 1; off >>= 1) {
        #pragma unroll
        for (int j = 0; j < 64; j++) {
            ULL o = __shfl_xor_sync(0xffffffffu, acc[j], off);
            float2 a = unpack2(acc[j]);
            float2 c = unpack2(o);
            acc[j] = pack2(fmaxf(a.x, c.x), fmaxf(a.y, c.y));
        }
    }

    // ---- output: lane k owns channels [8k, 8k+8); static register indices ----
    const int base = (b * NS_SZ + n) * OUTC;
    #pragma unroll
    for (int j4 = 0; j4 < 16; j4++) {
        if (k == j4) {
            float2 p0 = unpack2(acc[j4*4 + 0]);
            float2 p1 = unpack2(acc[j4*4 + 1]);
            float2 p2 = unpack2(acc[j4*4 + 2]);
            float2 p3 = unpack2(acc[j4*4 + 3]);
            float4 o0 = make_float4(p0.x, p0.y, p1.x, p1.y);
            float4 o1 = make_float4(p2.x, p2.y, p3.x, p3.y);
            const int off = base + j4 * 8;
            *(float4*)(out + off)     = o0;
            *(float4*)(out + off + 4) = o1;
            if (copies > 1) {
                *(float4*)(out + OUT_ONE + off)     = o0;
                *(float4*)(out + OUT_ONE + off + 4) = o1;
            }
        }
    }
}

extern "C" void kernel_launch(void* const* d_in, const int* in_sizes, int n_in,
                              void* d_out, int out_size)
{
    const float* xyz   = (const float*)d_in[0];
    const float* pts   = (const float*)d_in[1];
    const float* xyzs  = (const float*)d_in[2];
    const int*   nbr   = (const int*)  d_in[3];
    const float* vmask = (const float*)d_in[4];
    const float* w0  = (const float*)d_in[5];
    const float* b0  = (const float*)d_in[6];
    const float* g0  = (const float*)d_in[7];
    const float* be0 = (const float*)d_in[8];
    const float* m0  = (const float*)d_in[9];
    const float* v0  = (const float*)d_in[10];
    const float* w1  = (const float*)d_in[11];
    const float* b1  = (const float*)d_in[12];
    const float* g1  = (const float*)d_in[13];
    const float* be1 = (const float*)d_in[14];
    const float* m1  = (const float*)d_in[15];
    const float* v1  = (const float*)d_in[16];
    const float* w2  = (const float*)d_in[17];
    const float* b2  = (const float*)d_in[18];
    const float* g2  = (const float*)d_in[19];
    const float* be2 = (const float*)d_in[20];
    const float* m2  = (const float*)d_in[21];
    const float* v2  = (const float*)d_in[22];

    int copies = (out_size >= 2 * OUT_ONE) ? 2 : 1;

    cudaFuncSetAttribute(pointnet_sa_kernel,
                         cudaFuncAttributeMaxDynamicSharedMemorySize, SMEM_BYTES);

    const int groups = B_SZ * NS_SZ;                       // 65536
    const int blocks = groups / (THREADS / K_SZ);          // 4096
    pointnet_sa_kernel<<<blocks, THREADS, SMEM_BYTES>>>(
        xyz, pts, xyzs, nbr, vmask,
        w0, b0, g0, be0, m0, v0,
        w1, b1, g1, be1, m1, v1,
        w2, b2, g2, be2, m2, v2,
        (float*)d_out, copies);
}